// round 6
// baseline (speedup 1.0000x reference)
#include <cuda_runtime.h>
#include <math.h>

// Problem constants
#define N3   3072   // 3 * N_SERIES nodes
#define NMID 1024   // cropped middle N
#define NBC  4096   // B*C = 64*64 (also B*H for outputs)

// Single scratch buffer (depth-0 GLU output). 50 MB.
__device__ float g_H1[(size_t)N3 * NBC];

// ---------------------------------------------------------------------------
// Fused SGEMM + GLU:  C = A(M,K) @ B(K,4096), then per output tile compute
//   out[v, b*64+h] = (bias[h] + W[h,:].g) * sigmoid(bias[h+64] + W[h+64,:].g)
// where g = C[v, b*64 + 0..63].  Optional elementwise max with maxsrc.
// BM=BN=128, BK=16, 256 threads, 8x8 microtile. N fixed at 4096.
// A 128-wide tile spans exactly 2 complete b-groups of 64 channels, so the
// GLU (which mixes only across c) is tile-local. The tile is staged through
// smem in 32-row chunks (reusing the As/Bs union) for the epilogue.
// ---------------------------------------------------------------------------
__global__ __launch_bounds__(256, 2) void sgemm_glu_k(
    int K,
    const float* __restrict__ A,
    const float* __restrict__ B,
    const float* __restrict__ W,      // (128, 64)
    const float* __restrict__ bias,   // (128,)
    const float* __restrict__ maxsrc, // nullptr, or (Mout, 4096) aligned w/ out
    float* __restrict__ out)          // (Mout, 4096)
{
    constexpr int BM = 128, BN = 128, BK = 16, TM = 8, TN = 8;
    // Union: mainloop uses [0,2048) = As, [2048,4096) = Bs (16 KB);
    // epilogue reuses [0,4352) as the 64x68 padded chunk buffer (17.4 KB).
    __shared__ float smem[4608];
    float* As = smem;          // As[k][m] : BK x BM, A stored transposed
    float* Bs = smem + 2048;   // Bs[k][n] : BK x BN

    const int tid = threadIdx.x;
    const int bx = blockIdx.x, by = blockIdx.y;
    A += (size_t)by * BM * K;
    B += bx * BN;

    const int rA = tid >> 2;         // 0..63
    const int cA = (tid & 3) << 2;   // 0,4,8,12
    const int rB = tid >> 5;         // 0..7
    const int cB = (tid & 31) << 2;  // 0..124
    const int tRow = (tid >> 4) * TM;
    const int tCol = (tid & 15) * TN;

    float acc[TM][TN] = {};
    float rM[TM], rN[TN];

    for (int k0 = 0; k0 < K; k0 += BK) {
        #pragma unroll
        for (int off = 0; off < BM; off += 64) {
            float4 v = *reinterpret_cast<const float4*>(&A[(size_t)(rA + off) * K + cA]);
            As[(cA + 0) * BM + rA + off] = v.x;
            As[(cA + 1) * BM + rA + off] = v.y;
            As[(cA + 2) * BM + rA + off] = v.z;
            As[(cA + 3) * BM + rA + off] = v.w;
        }
        #pragma unroll
        for (int off = 0; off < BK; off += 8) {
            *reinterpret_cast<float4*>(&Bs[(rB + off) * BN + cB]) =
                *reinterpret_cast<const float4*>(&B[(size_t)(rB + off) * NBC + cB]);
        }
        __syncthreads();
        A += BK;
        B += (size_t)BK * NBC;

        #pragma unroll
        for (int k = 0; k < BK; k++) {
            #pragma unroll
            for (int i = 0; i < TM; i += 4)
                *reinterpret_cast<float4*>(&rM[i]) =
                    *reinterpret_cast<const float4*>(&As[k * BM + tRow + i]);
            #pragma unroll
            for (int j = 0; j < TN; j += 4)
                *reinterpret_cast<float4*>(&rN[j]) =
                    *reinterpret_cast<const float4*>(&Bs[k * BN + tCol + j]);
            #pragma unroll
            for (int i = 0; i < TM; i++)
                #pragma unroll
                for (int j = 0; j < TN; j++)
                    acc[i][j] += rM[i] * rN[j];
        }
        __syncthreads();
    }

    // ---------------- Fused GLU epilogue, 4 chunks of 32 tile-rows ----------
    // gs layout: (local_row r in 0..31, b2 in 0..1) -> row p2 = r*2+b2,
    //            gs[p2*68 + c], c in 0..63.  (68 pad kills bank conflicts)
    float* gs = smem;
    const int b2w   = tCol >> 6;       // which b-group this thread's cols hit
    const int cOff  = tCol & 63;       // channel offset of this thread's cols
    const int pair  = tid >> 2;        // 0..63 : (v_local, b2) pair
    const int h0    = (tid & 3) << 4;  // 16 h-values per thread
    const int vLoc  = pair >> 1;
    const int b2r   = pair & 1;

    #pragma unroll 1
    for (int ch = 0; ch < 4; ch++) {
        // writers: threads whose 8 rows fall in [32ch, 32ch+32)
        if ((tRow >> 5) == ch) {
            const int r0 = tRow - (ch << 5);
            #pragma unroll
            for (int i = 0; i < TM; i++) {
                int p2 = (r0 + i) * 2 + b2w;
                *reinterpret_cast<float4*>(&gs[p2 * 68 + cOff]) =
                    make_float4(acc[i][0], acc[i][1], acc[i][2], acc[i][3]);
                *reinterpret_cast<float4*>(&gs[p2 * 68 + cOff + 4]) =
                    make_float4(acc[i][4], acc[i][5], acc[i][6], acc[i][7]);
            }
        }
        __syncthreads();

        // all 256 threads: GLU for 64 pairs x 64 h  (16 h per thread)
        const float* grow = &gs[pair * 68];
        const size_t orow = (size_t)((by << 7) + (ch << 5) + vLoc) * NBC
                          + (bx << 7) + (b2r << 6);
        #pragma unroll 4
        for (int hq = 0; hq < 4; hq++) {
            float v4[4];
            #pragma unroll
            for (int hs = 0; hs < 4; hs++) {
                const int h = h0 + hq * 4 + hs;
                float accL = __ldg(&bias[h]);
                float accR = __ldg(&bias[h + 64]);
                const float4* wl = reinterpret_cast<const float4*>(W + h * 64);
                const float4* wr = reinterpret_cast<const float4*>(W + (h + 64) * 64);
                #pragma unroll
                for (int c4 = 0; c4 < 16; c4++) {
                    float4 g = *reinterpret_cast<const float4*>(&grow[c4 * 4]);
                    float4 a = __ldg(wl + c4);
                    float4 r = __ldg(wr + c4);
                    accL += a.x * g.x + a.y * g.y + a.z * g.z + a.w * g.w;
                    accR += r.x * g.x + r.y * g.y + r.z * g.z + r.w * g.w;
                }
                v4[hs] = accL / (1.0f + __expf(-accR));
            }
            if (maxsrc) {
                float4 m = *reinterpret_cast<const float4*>(&maxsrc[orow + h0 + hq * 4]);
                v4[0] = fmaxf(v4[0], m.x); v4[1] = fmaxf(v4[1], m.y);
                v4[2] = fmaxf(v4[2], m.z); v4[3] = fmaxf(v4[3], m.w);
            }
            *reinterpret_cast<float4*>(&out[orow + h0 + hq * 4]) =
                make_float4(v4[0], v4[1], v4[2], v4[3]);
        }
        __syncthreads();
    }
}

// ---------------------------------------------------------------------------
// Pipeline (2 launches):
//   H1  = GLU0( A @ X )                           (3072 x 4096)
//   out = max( H1[1024:2048],
//              GLU1( A[1024:2048] @ H1 ) )        (1024 x 4096)
// ---------------------------------------------------------------------------
extern "C" void kernel_launch(void* const* d_in, const int* in_sizes, int n_in,
                              void* d_out, int out_size)
{
    const float* x  = (const float*)d_in[0];  // (3072, 64, 64): [w][b*64+c]
    const float* A  = (const float*)d_in[1];  // (3072, 3072)
    const float* W0 = (const float*)d_in[2];
    const float* b0 = (const float*)d_in[3];
    const float* W1 = (const float*)d_in[4];
    const float* b1 = (const float*)d_in[5];
    float* out = (float*)d_out;

    float* H1 = nullptr;
    cudaGetSymbolAddress((void**)&H1, g_H1);
    if (!H1) return;

    dim3 blk(256);
    sgemm_glu_k<<<dim3(NBC / 128, N3 / 128), blk>>>(
        N3, A, x, W0, b0, nullptr, H1);
    sgemm_glu_k<<<dim3(NBC / 128, NMID / 128), blk>>>(
        N3, A + (size_t)NMID * N3, H1, W1, b1,
        H1 + (size_t)NMID * NBC, out);
}

// round 9
// speedup vs baseline: 1.2365x; 1.2365x over previous
#include <cuda_runtime.h>
#include <cstdint>
#include <math.h>

#define KDIM 3072
#define NBC  4096
#define NMID 1024

__device__ float g_H1[(size_t)3072 * 4096];  // depth-0 GLU output

__device__ __forceinline__ uint32_t s2u(const void* p) {
    uint32_t a;
    asm("{\n.reg .u64 t;\ncvta.to.shared.u64 t,%1;\ncvt.u32.u64 %0,t;\n}" : "=r"(a) : "l"(p));
    return a;
}
__device__ __forceinline__ void ldsm4(uint32_t* r, uint32_t addr) {
    asm volatile("ldmatrix.sync.aligned.m8n8.x4.shared.b16 {%0,%1,%2,%3},[%4];"
                 : "=r"(r[0]), "=r"(r[1]), "=r"(r[2]), "=r"(r[3]) : "r"(addr));
}
__device__ __forceinline__ void mma8(float* d, const uint32_t* a, const uint32_t* b) {
    asm volatile("mma.sync.aligned.m16n8k8.row.col.f32.tf32.tf32.f32 "
                 "{%0,%1,%2,%3},{%4,%5,%6,%7},{%8,%9},{%0,%1,%2,%3};"
                 : "+f"(d[0]), "+f"(d[1]), "+f"(d[2]), "+f"(d[3])
                 : "r"(a[0]), "r"(a[1]), "r"(a[2]), "r"(a[3]), "r"(b[0]), "r"(b[1]));
}
__device__ __forceinline__ void cpasync16(uint32_t dst, const void* src) {
    asm volatile("cp.async.cg.shared.global [%0],[%1],16;" :: "r"(dst), "l"(src));
}

// ---------------------------------------------------------------------------
// D[v,bc] = sum_w Ag[v,w]*Bg[w,bc] via mma.sync tf32, fused GLU (+max).
// BM=BN=128, BK=16, double-buffered. smem float[10240]:
//   stage s at s*5120 floats: As (128 rows x 16 k, pitch 20) then Bs
//   (128 n x 16 k, pitch 20, n-major = col-major for the mma).
// Epilogue reuses smem[0..4352) as 64x68 padded (v,b2)-pair buffer.
// ---------------------------------------------------------------------------
__global__ __launch_bounds__(256, 2) void mma_glu_k(
    const float* __restrict__ Ag,     // (Mrows, 3072) band base
    const float* __restrict__ Bg,     // (3072, 4096)
    const float* __restrict__ W,      // (128, 64)
    const float* __restrict__ bias,   // (128,)
    const float* __restrict__ maxsrc, // nullptr or aligned with out
    float* __restrict__ out)          // (Mrows, 4096)
{
    __shared__ float smem[10240];
    const uint32_t smb = s2u(smem);
    const int tid = threadIdx.x, lane = tid & 31, wid = tid >> 5;
    const int bx = blockIdx.x, by = blockIdx.y;
    const int wm = wid >> 2, wn = wid & 3;   // warp grid 2 (m) x 4 (n)

    // ldmatrix address components. PTX fragment tables:
    //  A (m16n8k8 tf32): matrix order m0=(r0-7,k0-3) m1=(r8-15,k0-3)
    //                    m2=(r0-7,k4-7) m3=(r8-15,k4-7)
    //      -> lane bit3: +8 rows, lane bit4: +16B (k+4)
    //  B: regs {0,1}=(n0-7,k0-3),(n0-7,k4-7); {2,3}=(n8-15,...)
    //      -> lane bit3: +16B (k+4), lane bit4: +8 n-rows
    const int arow = (lane & 7) + ((lane >> 3) & 1) * 8;
    const int ab16 = ((lane >> 4) & 1) * 16;
    const int brow = (lane & 7) + ((lane >> 4) & 1) * 8;
    const int bb16 = ((lane >> 3) & 1) * 16;
    uint32_t aoff[4], boff[2];
    #pragma unroll
    for (int g = 0; g < 4; g++) aoff[g] = (wm * 64 + g * 16 + arow) * 80 + ab16;
    #pragma unroll
    for (int h = 0; h < 2; h++) boff[h] = 10240 + (wn * 32 + h * 16 + brow) * 80 + bb16;

    // loaders
    const float* aSrc = Ag + (size_t)(by * 128 + (tid >> 1)) * KDIM + (tid & 1) * 8;
    const uint32_t aDst = (tid >> 1) * 20 + (tid & 1) * 8;  // float idx in As
    const int bn = tid & 127, bkq = tid >> 7;               // n, k-half
    const float* bSrc = Bg + (size_t)bx * 128 + bn;
    const uint32_t bDst = 2560 + bn * 20 + bkq * 8;         // float idx in Bs
    float bR[8];

    auto ldgB = [&](int c) {
        const size_t kb = (size_t)(c * 16 + bkq * 8) * NBC;
        #pragma unroll
        for (int j = 0; j < 8; j++) bR[j] = bSrc[kb + (size_t)j * NBC];
    };
    auto cpA = [&](int c, int s) {
        uint32_t d = smb + (s * 5120 + aDst) * 4;
        cpasync16(d, aSrc + c * 16);
        cpasync16(d + 16, aSrc + c * 16 + 4);
        asm volatile("cp.async.commit_group;");
    };
    auto stsB = [&](int s) {
        float* p = smem + s * 5120 + bDst;
        *(float4*)p = make_float4(bR[0], bR[1], bR[2], bR[3]);
        *(float4*)(p + 4) = make_float4(bR[4], bR[5], bR[6], bR[7]);
    };

    float acc[4][4][4] = {};

    // prologue: fill stage 0
    cpA(0, 0);
    ldgB(0);
    stsB(0);
    asm volatile("cp.async.wait_group 0;");
    __syncthreads();

    for (int c = 0; c < 192; c++) {
        const int s = c & 1;
        if (c < 191) { cpA(c + 1, s ^ 1); ldgB(c + 1); }

        const uint32_t sb = smb + s * 20480;
        uint32_t a[4][4], b[2][4];
        #pragma unroll
        for (int ks = 0; ks < 2; ks++) {
            #pragma unroll
            for (int g = 0; g < 4; g++) ldsm4(a[g], sb + aoff[g] + ks * 32);
            #pragma unroll
            for (int h = 0; h < 2; h++) ldsm4(b[h], sb + boff[h] + ks * 32);
            #pragma unroll
            for (int g = 0; g < 4; g++)
                #pragma unroll
                for (int f = 0; f < 4; f++)
                    mma8(acc[g][f], a[g], &b[f >> 1][(f & 1) * 2]);
        }

        if (c < 191) { stsB(s ^ 1); asm volatile("cp.async.wait_group 0;"); }
        __syncthreads();
    }

    // ---------------- fused GLU epilogue, 4 chunks of 32 tile-rows ----------
    // acc layout: c0,c1 = (row=lane>>2, n=(lane&3)*2+{0,1}), c2,c3 = row+8.
    float* gs = smem;                 // [p2 = local_row*2 + b2][c], pitch 68
    const int pair = tid >> 2;        // (v_local, b2) pair within chunk
    const int h0 = (tid & 3) << 4;    // 16 h per thread
    const int vLoc = pair >> 1, b2r = pair & 1;

    #pragma unroll 1
    for (int ch = 0; ch < 4; ch++) {
        if (wm == (ch >> 1)) {
            #pragma unroll
            for (int gg = 0; gg < 2; gg++) {
                const int g = (ch & 1) * 2 + gg;
                #pragma unroll
                for (int f = 0; f < 4; f++) {
                    const int n0 = wn * 32 + f * 8 + (lane & 3) * 2;
                    const int b2 = n0 >> 6, cc = n0 & 63;
                    const int lr = gg * 16 + (lane >> 2);
                    *(float2*)&gs[(lr * 2 + b2) * 68 + cc] =
                        make_float2(acc[g][f][0], acc[g][f][1]);
                    *(float2*)&gs[((lr + 8) * 2 + b2) * 68 + cc] =
                        make_float2(acc[g][f][2], acc[g][f][3]);
                }
            }
        }
        __syncthreads();

        const float* grow = &gs[pair * 68];
        const size_t orow = (size_t)((by << 7) + (ch << 5) + vLoc) * NBC
                          + (bx << 7) + (b2r << 6);
        #pragma unroll 4
        for (int hq = 0; hq < 4; hq++) {
            float v4[4];
            #pragma unroll
            for (int hs = 0; hs < 4; hs++) {
                const int h = h0 + hq * 4 + hs;
                float accL = __ldg(&bias[h]);
                float accR = __ldg(&bias[h + 64]);
                const float4* wl = (const float4*)(W + h * 64);
                const float4* wr = (const float4*)(W + (h + 64) * 64);
                #pragma unroll
                for (int c4 = 0; c4 < 16; c4++) {
                    float4 g = *(const float4*)(grow + c4 * 4);
                    float4 a = __ldg(wl + c4), r = __ldg(wr + c4);
                    accL += a.x * g.x + a.y * g.y + a.z * g.z + a.w * g.w;
                    accR += r.x * g.x + r.y * g.y + r.z * g.z + r.w * g.w;
                }
                v4[hs] = __fdividef(accL, 1.0f + __expf(-accR));
            }
            if (maxsrc) {
                float4 m = *(const float4*)(maxsrc + orow + h0 + hq * 4);
                v4[0] = fmaxf(v4[0], m.x); v4[1] = fmaxf(v4[1], m.y);
                v4[2] = fmaxf(v4[2], m.z); v4[3] = fmaxf(v4[3], m.w);
            }
            *(float4*)(out + orow + h0 + hq * 4) = make_float4(v4[0], v4[1], v4[2], v4[3]);
        }
        __syncthreads();
    }
}

extern "C" void kernel_launch(void* const* d_in, const int* in_sizes, int n_in,
                              void* d_out, int out_size)
{
    const float* x  = (const float*)d_in[0];
    const float* A  = (const float*)d_in[1];
    const float* W0 = (const float*)d_in[2];
    const float* b0 = (const float*)d_in[3];
    const float* W1 = (const float*)d_in[4];
    const float* b1 = (const float*)d_in[5];
    float* out = (float*)d_out;

    float* H1 = nullptr;
    cudaGetSymbolAddress((void**)&H1, g_H1);
    if (!H1) return;

    mma_glu_k<<<dim3(32, 24), 256>>>(A, x, W0, b0, nullptr, H1);
    mma_glu_k<<<dim3(32, 8), 256>>>(A + (size_t)NMID * KDIM, H1, W1, b1,
                                    H1 + (size_t)NMID * NBC, out);
}